// round 6
// baseline (speedup 1.0000x reference)
#include <cuda_runtime.h>
#include <cuda_fp16.h>
#include <cstdint>
#include <math.h>

// Problem constants
#define L      2048
#define DIM    4096
#define NH     32
#define NKV    8
#define HD     128
#define QDIM   (NH*HD)    // 4096
#define KVDIM  (NKV*HD)   // 1024
#define ATT_SCALE 0.08838834764831845f  // 128^-0.5

// ---------------------------------------------------------------------------
// Scratch (__device__ globals; no allocations allowed)
// ---------------------------------------------------------------------------
__device__ float g_q[L*QDIM];                 // q fp32 (pre-rope)
__device__ float g_kv[L*2*KVDIM];             // [L][k(1024) | v(1024)] fp32
__device__ float g_attn[L*QDIM];              // attention output fp32
__device__ __half g_qh[L*QDIM];               // q fp16, roped, *ATT_SCALE
__device__ __half g_kh[L*KVDIM];              // k fp16, roped
__device__ __half g_vh[L*KVDIM];              // v fp16

// int8 limbs + scales
__device__ int8_t g_xq0[L*DIM],  g_xq1[L*DIM];
__device__ int8_t g_aq0[L*QDIM], g_aq1[L*QDIM];
__device__ int8_t g_wq0[DIM*QDIM],   g_wq1[DIM*QDIM];       // wq^T  [N=4096][K=4096]
__device__ int8_t g_wkv0[2*KVDIM*DIM], g_wkv1[2*KVDIM*DIM]; // (wk|wv)^T [N=2048][K=4096]
__device__ int8_t g_wo0[QDIM*DIM],   g_wo1[QDIM*DIM];       // wo^T  [N=4096][K=4096]
__device__ float g_alx[L], g_alat[L];
__device__ float g_alwq[QDIM], g_alkv[2*KVDIM], g_alwo[DIM];

// ---------------------------------------------------------------------------
// PTX helpers (sm_80-era; valid on base compute_103 target)
// ---------------------------------------------------------------------------
__device__ __forceinline__ uint32_t smem_u32(const void* p) {
    uint32_t a;
    asm("{ .reg .u64 t; cvta.to.shared.u64 t, %1; cvt.u32.u64 %0, t; }" : "=r"(a) : "l"(p));
    return a;
}
__device__ __forceinline__ void cp16(void* smem, const void* g) {
    uint32_t s = smem_u32(smem);
    asm volatile("cp.async.cg.shared.global [%0], [%1], 16;" :: "r"(s), "l"(g));
}
#define CP_COMMIT() asm volatile("cp.async.commit_group;")
#define CP_WAIT0()  asm volatile("cp.async.wait_group 0;")
#define CP_WAIT1()  asm volatile("cp.async.wait_group 1;")

__device__ __forceinline__ void ldsm4(uint32_t* r, uint32_t addr) {
    asm volatile("ldmatrix.sync.aligned.m8n8.x4.shared.b16 {%0,%1,%2,%3}, [%4];"
                 : "=r"(r[0]), "=r"(r[1]), "=r"(r[2]), "=r"(r[3]) : "r"(addr));
}
__device__ __forceinline__ void ldsm4t(uint32_t* r, uint32_t addr) {
    asm volatile("ldmatrix.sync.aligned.m8n8.x4.trans.shared.b16 {%0,%1,%2,%3}, [%4];"
                 : "=r"(r[0]), "=r"(r[1]), "=r"(r[2]), "=r"(r[3]) : "r"(addr));
}
__device__ __forceinline__ void mma_f16(float* c, const uint32_t* a, const uint32_t* b) {
    asm volatile("mma.sync.aligned.m16n8k16.row.col.f32.f16.f16.f32 "
                 "{%0,%1,%2,%3},{%4,%5,%6,%7},{%8,%9},{%0,%1,%2,%3};"
                 : "+f"(c[0]), "+f"(c[1]), "+f"(c[2]), "+f"(c[3])
                 : "r"(a[0]), "r"(a[1]), "r"(a[2]), "r"(a[3]), "r"(b[0]), "r"(b[1]));
}
__device__ __forceinline__ void mma_s8(int* c, const uint32_t* a, const uint32_t* b) {
    asm volatile("mma.sync.aligned.m16n8k32.row.col.s32.s8.s8.s32 "
                 "{%0,%1,%2,%3},{%4,%5,%6,%7},{%8,%9},{%0,%1,%2,%3};"
                 : "+r"(c[0]), "+r"(c[1]), "+r"(c[2]), "+r"(c[3])
                 : "r"(a[0]), "r"(a[1]), "r"(a[2]), "r"(a[3]), "r"(b[0]), "r"(b[1]));
}
__device__ __forceinline__ uint32_t pack_h2(float lo, float hi) {
    uint32_t r;
    asm("cvt.rn.f16x2.f32 %0, %1, %2;" : "=r"(r) : "f"(hi), "f"(lo));
    return r;
}

// ---------------------------------------------------------------------------
// Quantization: fp32 -> 2x int8 limbs.  x = alpha*(q0 + q1/254), alpha=max/127
// ---------------------------------------------------------------------------
// Per-row quant for activation matrices with row length 4096.
__global__ __launch_bounds__(256) void quant_rows(
    const float* __restrict__ X, int8_t* __restrict__ Q0,
    int8_t* __restrict__ Q1, float* __restrict__ alpha)
{
    const int row = blockIdx.x;
    const int tid = threadIdx.x;
    const float* xr = X + (size_t)row * 4096;
    float vals[16];
    float mx = 1e-20f;
    #pragma unroll
    for (int c = 0; c < 4; c++) {
        float4 v = *(const float4*)(xr + c * 1024 + tid * 4);
        vals[c*4+0] = v.x; vals[c*4+1] = v.y; vals[c*4+2] = v.z; vals[c*4+3] = v.w;
        mx = fmaxf(mx, fmaxf(fmaxf(fabsf(v.x), fabsf(v.y)), fmaxf(fabsf(v.z), fabsf(v.w))));
    }
    __shared__ float red[8];
    #pragma unroll
    for (int o = 16; o > 0; o >>= 1) mx = fmaxf(mx, __shfl_xor_sync(0xFFFFFFFF, mx, o));
    if ((tid & 31) == 0) red[tid >> 5] = mx;
    __syncthreads();
    if (tid == 0) {
        float m = red[0];
        #pragma unroll
        for (int j = 1; j < 8; j++) m = fmaxf(m, red[j]);
        red[0] = m;
        alpha[row] = m / 127.0f;
    }
    __syncthreads();
    const float inva = 127.0f / red[0];
    #pragma unroll
    for (int c = 0; c < 4; c++) {
        char q0[4], q1[4];
        #pragma unroll
        for (int j = 0; j < 4; j++) {
            float r0 = vals[c*4+j] * inva;
            int i0 = __float2int_rn(r0);
            int i1 = __float2int_rn((r0 - (float)i0) * 254.0f);
            q0[j] = (char)i0; q1[j] = (char)i1;
        }
        *(char4*)(Q0 + (size_t)row * 4096 + c * 1024 + tid * 4) = make_char4(q0[0], q0[1], q0[2], q0[3]);
        *(char4*)(Q1 + (size_t)row * 4096 + c * 1024 + tid * 4) = make_char4(q1[0], q1[1], q1[2], q1[3]);
    }
}

// Per-column abs-max of W [K][N] -> alpha[n] = max/127
__global__ void colmax_kernel(const float* __restrict__ W, float* __restrict__ alpha,
                              int K, int N)
{
    const int n0 = blockIdx.x * 32;
    const int tx = threadIdx.x, ty = threadIdx.y;
    float m = 1e-20f;
    for (int k = ty; k < K; k += 8)
        m = fmaxf(m, fabsf(W[(size_t)k * N + n0 + tx]));
    __shared__ float s[8][32];
    s[ty][tx] = m;
    __syncthreads();
    if (ty == 0) {
        #pragma unroll
        for (int j = 1; j < 8; j++) m = fmaxf(m, s[j][tx]);
        alpha[n0 + tx] = m / 127.0f;
    }
}

// Transpose + quantize: W [K][N] fp32 -> Q0,Q1 int8 [N][K]
__global__ void quantWT_kernel(const float* __restrict__ W, const float* __restrict__ alpha,
                               int8_t* __restrict__ Q0, int8_t* __restrict__ Q1, int K, int N)
{
    __shared__ float t[32][33];
    int n0 = blockIdx.x * 32, k0 = blockIdx.y * 32;
    int tx = threadIdx.x, ty = threadIdx.y;
    #pragma unroll
    for (int r = ty; r < 32; r += 8)
        t[r][tx] = W[(size_t)(k0 + r) * N + n0 + tx];
    __syncthreads();
    #pragma unroll
    for (int r = ty; r < 32; r += 8) {
        float inva = 1.0f / alpha[n0 + r];
        float r0 = t[tx][r] * inva;            // = W[k0+tx][n0+r]/alpha
        int i0 = __float2int_rn(r0);
        int i1 = __float2int_rn((r0 - (float)i0) * 254.0f);
        Q0[(size_t)(n0 + r) * K + k0 + tx] = (int8_t)i0;
        Q1[(size_t)(n0 + r) * K + k0 + tx] = (int8_t)i1;
    }
}

// ---------------------------------------------------------------------------
// int8 limb GEMM:  C[M,N] = A[M,K] @ B^T[N,K]  with
//   A = aA[m]*(A0 + A1/254),  B = aB[n]*(B0 + B1/254)
// Block 128x128, BK=128 int8, 8 warps (2M x 4N), warp tile 64x32.
// smem rows: 64 b16-units + 8 pad = GST 72 units (144 B) -> conflict-free ldsm.
// 2-stage cp.async pipeline. mma.m16n8k32.s8 (fragment layout == f16 in b16 view).
// ---------------------------------------------------------------------------
#define GST   72                 // b16 units per smem row
#define GBUFB (128*GST*2)        // bytes per stage per array = 18432

__global__ __launch_bounds__(256, 1) void gemm_i8(
    const int8_t* __restrict__ A0, const int8_t* __restrict__ A1,
    const int8_t* __restrict__ B0, const int8_t* __restrict__ B1,
    const float* __restrict__ aA, const float* __restrict__ aB,
    float* __restrict__ C, int M, int N, int K)
{
    extern __shared__ char dyn_smem[];
    const uint32_t sb = smem_u32(dyn_smem);
    const int tid = threadIdx.x, lane = tid & 31, wid = tid >> 5;
    const int wm = (wid & 1) * 64, wn = (wid >> 1) * 32;
    const int lrow = lane & 15, lcol = (lane >> 4) * 8;   // b16 units
    const int m0 = blockIdx.y * 128, n0 = blockIdx.x * 128;

    const int8_t* gA0 = A0 + (size_t)m0 * K;
    const int8_t* gA1 = A1 + (size_t)m0 * K;
    const int8_t* gB0 = B0 + (size_t)n0 * K;
    const int8_t* gB1 = B1 + (size_t)n0 * K;

    int acc0[4][4][4] = {};
    int acc1[4][4][4] = {};
    const int nit = K / 128;

    auto load_stage = [&](int it) {
        const int s = it & 1;
        const int k0 = it * 128;          // int8 offset
        for (int i = tid; i < 1024; i += 256) {
            int row = i >> 3, c = i & 7;  // 8 chunks of 16B = 128 int8 per row
            uint32_t so = (uint32_t)(row * 144 + c * 16);
            size_t go = (size_t)row * K + k0 + c * 16;
            cp16(dyn_smem + (0 * 2 + s) * GBUFB + so, gA0 + go);
            cp16(dyn_smem + (1 * 2 + s) * GBUFB + so, gA1 + go);
            cp16(dyn_smem + (2 * 2 + s) * GBUFB + so, gB0 + go);
            cp16(dyn_smem + (3 * 2 + s) * GBUFB + so, gB1 + go);
        }
        CP_COMMIT();
    };

    load_stage(0);

    for (int it = 0; it < nit; it++) {
        const int s = it & 1;
        if (it + 1 < nit) { load_stage(it + 1); CP_WAIT1(); }
        else              { CP_WAIT0(); }
        __syncthreads();

        const uint32_t a0b = sb + (uint32_t)((0 * 2 + s) * GBUFB);
        const uint32_t a1b = sb + (uint32_t)((1 * 2 + s) * GBUFB);
        const uint32_t b0b = sb + (uint32_t)((2 * 2 + s) * GBUFB);
        const uint32_t b1b = sb + (uint32_t)((3 * 2 + s) * GBUFB);

        #pragma unroll
        for (int ks = 0; ks < 4; ks++) {     // 4 slices of k32 (16 b16-units each)
            uint32_t a0[4][4], a1[4][4], b0[4][2], b1[4][2];
            #pragma unroll
            for (int mi = 0; mi < 4; mi++) {
                uint32_t off = (uint32_t)((wm + mi * 16 + lrow) * GST + ks * 16 + lcol) * 2;
                ldsm4(a0[mi], a0b + off);
                ldsm4(a1[mi], a1b + off);
            }
            #pragma unroll
            for (int nh = 0; nh < 2; nh++) {
                uint32_t off = (uint32_t)((wn + nh * 16 + lrow) * GST + ks * 16 + lcol) * 2;
                uint32_t r[4], q[4];
                ldsm4(r, b0b + off);
                ldsm4(q, b1b + off);
                b0[nh*2][0] = r[0]; b0[nh*2][1] = r[2];
                b0[nh*2+1][0] = r[1]; b0[nh*2+1][1] = r[3];
                b1[nh*2][0] = q[0]; b1[nh*2][1] = q[2];
                b1[nh*2+1][0] = q[1]; b1[nh*2+1][1] = q[3];
            }
            #pragma unroll
            for (int mi = 0; mi < 4; mi++)
                #pragma unroll
                for (int nj = 0; nj < 4; nj++) {
                    mma_s8(acc0[mi][nj], a0[mi], b0[nj]);
                    mma_s8(acc1[mi][nj], a0[mi], b1[nj]);
                    mma_s8(acc1[mi][nj], a1[mi], b0[nj]);
                }
        }
        __syncthreads();
    }

    // Epilogue: dequantize
    const int g = lane >> 2;
    const float inv254 = 1.0f / 254.0f;
    #pragma unroll
    for (int mi = 0; mi < 4; mi++) {
        int row = m0 + wm + mi * 16 + g;
        float sA0 = aA[row], sA1 = aA[row + 8];
        #pragma unroll
        for (int nj = 0; nj < 4; nj++) {
            int col = n0 + wn + nj * 8 + 2 * (lane & 3);
            float sB0 = aB[col], sB1 = aB[col + 1];
            float v0 = ((float)acc0[mi][nj][0] + (float)acc1[mi][nj][0] * inv254) * sA0 * sB0;
            float v1 = ((float)acc0[mi][nj][1] + (float)acc1[mi][nj][1] * inv254) * sA0 * sB1;
            float v2 = ((float)acc0[mi][nj][2] + (float)acc1[mi][nj][2] * inv254) * sA1 * sB0;
            float v3 = ((float)acc0[mi][nj][3] + (float)acc1[mi][nj][3] * inv254) * sA1 * sB1;
            *(float2*)&C[(size_t)row * N + col]       = make_float2(v0, v1);
            *(float2*)&C[(size_t)(row + 8) * N + col] = make_float2(v2, v3);
        }
    }
}

// ---------------------------------------------------------------------------
// RoPE kernels (interleaved rotation, concat-layout angles)
// ---------------------------------------------------------------------------
__global__ void rope_q_kernel(const float* __restrict__ q, __half* __restrict__ qh)
{
    long idx = (long)blockIdx.x * blockDim.x + threadIdx.x;  // L*NH*64 pairs
    if (idx >= (long)L * NH * 64) return;
    int  p  = (int)(idx & 63);
    long th = idx >> 6;                 // t*NH + h
    int  t  = (int)(th >> 5);

    const float Cc = 0.14391156644565413f; // ln(10000)/64
    int j0 = 2 * p, j1 = 2 * p + 1;
    float a0 = (float)t * expf(-Cc * (float)(j0 & 63));
    float a1 = (float)t * expf(-Cc * (float)(j1 & 63));
    float c0, s0, c1, s1;
    sincosf(a0, &s0, &c0);
    sincosf(a1, &s1, &c1);

    const float* base = q + th * 128;
    float x0 = base[j0], x1 = base[j1];
    float y0 = (x0 * c0 - x1 * s0) * ATT_SCALE;
    float y1 = (x1 * c1 + x0 * s1) * ATT_SCALE;
    *(__half2*)(qh + th * 128 + j0) = __floats2half2_rn(y0, y1);
}

__global__ void rope_k_kernel(float* __restrict__ kv, __half* __restrict__ kh)
{
    long idx = (long)blockIdx.x * blockDim.x + threadIdx.x;  // L*NKV*64 pairs
    if (idx >= (long)L * NKV * 64) return;
    int  p  = (int)(idx & 63);
    long th = idx >> 6;                 // t*NKV + hk
    int  t  = (int)(th >> 3);
    int  hk = (int)(th & 7);

    const float Cc = 0.14391156644565413f;
    int j0 = 2 * p, j1 = 2 * p + 1;
    float a0 = (float)t * expf(-Cc * (float)(j0 & 63));
    float a1 = (float)t * expf(-Cc * (float)(j1 & 63));
    float c0, s0, c1, s1;
    sincosf(a0, &s0, &c0);
    sincosf(a1, &s1, &c1);

    float* base = kv + (size_t)t * 2048 + hk * 128;
    float x0 = base[j0], x1 = base[j1];
    float y0 = x0 * c0 - x1 * s0;
    float y1 = x1 * c1 + x0 * s1;
    base[j0] = y0;
    base[j1] = y1;
    *(__half2*)(kh + (size_t)t * KVDIM + hk * 128 + j0) = __floats2half2_rn(y0, y1);
}

__global__ void conv_vh_kernel(const float* __restrict__ kv, __half* __restrict__ vh)
{
    long idx = ((long)blockIdx.x * blockDim.x + threadIdx.x) * 2;
    if (idx >= (long)L * KVDIM) return;
    int t = (int)(idx >> 10), j = (int)(idx & 1023);
    float2 v = *(const float2*)(kv + (size_t)t * 2048 + 1024 + j);
    *(__half2*)(vh + idx) = __floats2half2_rn(v.x, v.y);
}

__global__ void write_kv_kernel(const float* __restrict__ kv,
                                float* __restrict__ ok, float* __restrict__ ov)
{
    long idx = (long)blockIdx.x * blockDim.x + threadIdx.x;
    const long total = (long)NH * L * HD;
    if (idx >= total) return;
    int h = (int)(idx >> 18);
    int rem = (int)(idx & 262143);
    int t = rem >> 7;
    int d = rem & 127;
    long src = (long)t * 2048 + (h >> 2) * HD + d;
    ok[idx] = kv[src];
    ov[idx] = kv[src + 1024];
}

// ---------------------------------------------------------------------------
// Flash attention on mma.sync fp16 (unchanged from round 5).
// ---------------------------------------------------------------------------
#define QS_ST 136
#define KV_ST 136
#define KOFF  (128*QS_ST)            // halves
#define VOFF  (KOFF + 2*64*KV_ST)
#define ATT_SMEM ((KOFF + 4*64*KV_ST) * 2)   // bytes = 104448

__global__ __launch_bounds__(256, 1) void attn_mma(
    const __half* __restrict__ qh, const __half* __restrict__ kh,
    const __half* __restrict__ vh, float* __restrict__ o)
{
    extern __shared__ char dyn_smem[];
    __half* smh = (__half*)dyn_smem;
    const uint32_t sb = smem_u32(smh);
    const int tid = threadIdx.x, lane = tid & 31, wid = tid >> 5;
    const int h = blockIdx.y, qt = blockIdx.x, kvh = h >> 2;
    const int g = lane >> 2;
    const int lrow = lane & 15, lcol = (lane >> 4) * 8;

    for (int i = tid; i < 2048; i += 256) {
        int r = i >> 4, c = i & 15;
        cp16(smh + r * QS_ST + c * 8,
             qh + (size_t)(qt * 128 + r) * QDIM + h * HD + c * 8);
    }
    CP_COMMIT(); CP_WAIT0();
    __syncthreads();
    uint32_t aQ[8][4];
    #pragma unroll
    for (int ks = 0; ks < 8; ks++)
        ldsm4(aQ[ks], sb + (uint32_t)((wid * 16 + lrow) * QS_ST + ks * 16 + lcol) * 2);

    auto load_kv = [&](int kt) {
        const int s = kt & 1;
        const __half* kg = kh + (size_t)(kt * 64) * KVDIM + kvh * HD;
        const __half* vg = vh + (size_t)(kt * 64) * KVDIM + kvh * HD;
        __half* ksm = smh + KOFF + s * (64 * KV_ST);
        __half* vsm = smh + VOFF + s * (64 * KV_ST);
        for (int i = tid; i < 1024; i += 256) {
            int r = i >> 4, c = i & 15;
            cp16(ksm + r * KV_ST + c * 8, kg + (size_t)r * KVDIM + c * 8);
            cp16(vsm + r * KV_ST + c * 8, vg + (size_t)r * KVDIM + c * 8);
        }
        CP_COMMIT();
    };

    float O[16][4] = {};
    float m0 = -1e30f, m1 = -1e30f, l0 = 0.f, l1 = 0.f;

    load_kv(0);

    for (int kt = 0; kt < 32; kt++) {
        if (kt + 1 < 32) { load_kv(kt + 1); CP_WAIT1(); }
        else             { CP_WAIT0(); }
        __syncthreads();

        const uint32_t kbase = sb + (uint32_t)(KOFF + (kt & 1) * (64 * KV_ST)) * 2;
        const uint32_t vbase = sb + (uint32_t)(VOFF + (kt & 1) * (64 * KV_ST)) * 2;

        float c[8][4] = {};
        #pragma unroll
        for (int ks = 0; ks < 8; ks++) {
            #pragma unroll
            for (int nh = 0; nh < 4; nh++) {
                uint32_t r[4];
                ldsm4(r, kbase + (uint32_t)((nh * 16 + lrow) * KV_ST + ks * 16 + lcol) * 2);
                uint32_t b0[2] = {r[0], r[2]};
                uint32_t b1[2] = {r[1], r[3]};
                mma_f16(c[nh * 2],     aQ[ks], b0);
                mma_f16(c[nh * 2 + 1], aQ[ks], b1);
            }
        }

        float mx0 = m0, mx1 = m1;
        #pragma unroll
        for (int t = 0; t < 8; t++) {
            mx0 = fmaxf(mx0, fmaxf(c[t][0], c[t][1]));
            mx1 = fmaxf(mx1, fmaxf(c[t][2], c[t][3]));
        }
        mx0 = fmaxf(mx0, __shfl_xor_sync(0xFFFFFFFF, mx0, 1));
        mx0 = fmaxf(mx0, __shfl_xor_sync(0xFFFFFFFF, mx0, 2));
        mx1 = fmaxf(mx1, __shfl_xor_sync(0xFFFFFFFF, mx1, 1));
        mx1 = fmaxf(mx1, __shfl_xor_sync(0xFFFFFFFF, mx1, 2));
        float f0 = __expf(m0 - mx0), f1 = __expf(m1 - mx1);
        m0 = mx0; m1 = mx1;
        float s0 = 0.f, s1 = 0.f;
        #pragma unroll
        for (int t = 0; t < 8; t++) {
            c[t][0] = __expf(c[t][0] - m0); s0 += c[t][0];
            c[t][1] = __expf(c[t][1] - m0); s0 += c[t][1];
            c[t][2] = __expf(c[t][2] - m1); s1 += c[t][2];
            c[t][3] = __expf(c[t][3] - m1); s1 += c[t][3];
        }
        s0 += __shfl_xor_sync(0xFFFFFFFF, s0, 1);
        s0 += __shfl_xor_sync(0xFFFFFFFF, s0, 2);
        s1 += __shfl_xor_sync(0xFFFFFFFF, s1, 1);
        s1 += __shfl_xor_sync(0xFFFFFFFF, s1, 2);
        l0 = l0 * f0 + s0;
        l1 = l1 * f1 + s1;

        #pragma unroll
        for (int t = 0; t < 16; t++) {
            O[t][0] *= f0; O[t][1] *= f0;
            O[t][2] *= f1; O[t][3] *= f1;
        }

        #pragma unroll
        for (int k2 = 0; k2 < 4; k2++) {
            uint32_t a[4];
            a[0] = pack_h2(c[2 * k2][0],     c[2 * k2][1]);
            a[1] = pack_h2(c[2 * k2][2],     c[2 * k2][3]);
            a[2] = pack_h2(c[2 * k2 + 1][0], c[2 * k2 + 1][1]);
            a[3] = pack_h2(c[2 * k2 + 1][2], c[2 * k2 + 1][3]);
            #pragma unroll
            for (int dj = 0; dj < 8; dj++) {
                uint32_t r[4];
                ldsm4t(r, vbase + (uint32_t)((k2 * 16 + lrow) * KV_ST + dj * 16 + lcol) * 2);
                uint32_t b0[2] = {r[0], r[1]};
                uint32_t b1[2] = {r[2], r[3]};
                mma_f16(O[dj * 2],     a, b0);
                mma_f16(O[dj * 2 + 1], a, b1);
            }
        }
        __syncthreads();
    }

    float inv0 = 1.f / l0, inv1 = 1.f / l1;
    const int row0 = qt * 128 + wid * 16 + g;
    #pragma unroll
    for (int t = 0; t < 16; t++) {
        float* d0 = o + (size_t)row0 * QDIM + h * HD + t * 8 + 2 * (lane & 3);
        float* d1 = o + (size_t)(row0 + 8) * QDIM + h * HD + t * 8 + 2 * (lane & 3);
        *(float2*)d0 = make_float2(O[t][0] * inv0, O[t][1] * inv0);
        *(float2*)d1 = make_float2(O[t][2] * inv1, O[t][3] * inv1);
    }
}

// ---------------------------------------------------------------------------
// Launch
// ---------------------------------------------------------------------------
extern "C" void kernel_launch(void* const* d_in, const int* in_sizes, int n_in,
                              void* d_out, int out_size)
{
    const float* x  = (const float*)d_in[0];
    const float* wq = (const float*)d_in[1];
    const float* wk = (const float*)d_in[2];
    const float* wv = (const float*)d_in[3];
    const float* wo = (const float*)d_in[4];
    float* out = (float*)d_out;

    float *pq, *pkv, *pattn, *palx, *palat, *palwq, *palkv, *palwo;
    __half *pqh, *pkh, *pvh;
    int8_t *pxq0, *pxq1, *paq0, *paq1, *pwq0, *pwq1, *pwkv0, *pwkv1, *pwo0, *pwo1;
    cudaGetSymbolAddress((void**)&pq,    g_q);
    cudaGetSymbolAddress((void**)&pkv,   g_kv);
    cudaGetSymbolAddress((void**)&pattn, g_attn);
    cudaGetSymbolAddress((void**)&pqh,   g_qh);
    cudaGetSymbolAddress((void**)&pkh,   g_kh);
    cudaGetSymbolAddress((void**)&pvh,   g_vh);
    cudaGetSymbolAddress((void**)&pxq0,  g_xq0);
    cudaGetSymbolAddress((void**)&pxq1,  g_xq1);
    cudaGetSymbolAddress((void**)&paq0,  g_aq0);
    cudaGetSymbolAddress((void**)&paq1,  g_aq1);
    cudaGetSymbolAddress((void**)&pwq0,  g_wq0);
    cudaGetSymbolAddress((void**)&pwq1,  g_wq1);
    cudaGetSymbolAddress((void**)&pwkv0, g_wkv0);
    cudaGetSymbolAddress((void**)&pwkv1, g_wkv1);
    cudaGetSymbolAddress((void**)&pwo0,  g_wo0);
    cudaGetSymbolAddress((void**)&pwo1,  g_wo1);
    cudaGetSymbolAddress((void**)&palx,  g_alx);
    cudaGetSymbolAddress((void**)&palat, g_alat);
    cudaGetSymbolAddress((void**)&palwq, g_alwq);
    cudaGetSymbolAddress((void**)&palkv, g_alkv);
    cudaGetSymbolAddress((void**)&palwo, g_alwo);

    const int gemm_smem = 8 * GBUFB;   // 147456 B
    cudaFuncSetAttribute(gemm_i8, cudaFuncAttributeMaxDynamicSharedMemorySize, gemm_smem);
    cudaFuncSetAttribute(attn_mma, cudaFuncAttributeMaxDynamicSharedMemorySize, ATT_SMEM);

    dim3 thr32x8(32, 8);

    // 1) Quantize activations and weights (int8 limbs)
    quant_rows<<<L, 256>>>(x, pxq0, pxq1, palx);
    colmax_kernel<<<QDIM / 32, thr32x8>>>(wq, palwq, DIM, QDIM);
    quantWT_kernel<<<dim3(QDIM / 32, DIM / 32), thr32x8>>>(wq, palwq, pwq0, pwq1, DIM, QDIM);
    colmax_kernel<<<KVDIM / 32, thr32x8>>>(wk, palkv, DIM, KVDIM);
    quantWT_kernel<<<dim3(KVDIM / 32, DIM / 32), thr32x8>>>(wk, palkv, pwkv0, pwkv1, DIM, KVDIM);
    colmax_kernel<<<KVDIM / 32, thr32x8>>>(wv, palkv + KVDIM, DIM, KVDIM);
    quantWT_kernel<<<dim3(KVDIM / 32, DIM / 32), thr32x8>>>(wv, palkv + KVDIM,
                                                            pwkv0 + (size_t)KVDIM * DIM,
                                                            pwkv1 + (size_t)KVDIM * DIM, DIM, KVDIM);
    colmax_kernel<<<DIM / 32, thr32x8>>>(wo, palwo, QDIM, DIM);
    quantWT_kernel<<<dim3(DIM / 32, QDIM / 32), thr32x8>>>(wo, palwo, pwo0, pwo1, QDIM, DIM);

    // 2) Projections: q = x@wq ; kv = x@(wk|wv)
    gemm_i8<<<dim3(QDIM / 128, L / 128), 256, gemm_smem>>>(
        pxq0, pxq1, pwq0, pwq1, palx, palwq, pq, L, QDIM, DIM);
    gemm_i8<<<dim3(2 * KVDIM / 128, L / 128), 256, gemm_smem>>>(
        pxq0, pxq1, pwkv0, pwkv1, palx, palkv, pkv, L, 2 * KVDIM, DIM);

    // 3) RoPE + fp16 conversions
    {
        long pq_pairs = (long)L * NH * 64;
        long pk_pairs = (long)L * NKV * 64;
        rope_q_kernel<<<(unsigned)((pq_pairs + 255) / 256), 256>>>(pq, pqh);
        rope_k_kernel<<<(unsigned)((pk_pairs + 255) / 256), 256>>>(pkv, pkh);
        long nv = (long)L * KVDIM / 2;
        conv_vh_kernel<<<(unsigned)((nv + 255) / 256), 256>>>(pkv, pvh);
    }

    // 4) Emit repeated (k, v) output sections
    const long OUT0 = (long)L * QDIM;
    const long KVSZ = (long)NH * L * HD;
    if ((long)out_size >= OUT0 + 2 * KVSZ) {
        write_kv_kernel<<<(unsigned)((KVSZ + 255) / 256), 256>>>(pkv, out + OUT0, out + OUT0 + KVSZ);
    }

    // 5) Flash attention (fp16 mma)
    attn_mma<<<dim3(L / 128, NH), 256, ATT_SMEM>>>(pqh, pkh, pvh, pattn);

    // 6) Quantize attention output, final projection
    quant_rows<<<L, 256>>>(pattn, paq0, paq1, palat);
    gemm_i8<<<dim3(DIM / 128, L / 128), 256, gemm_smem>>>(
        paq0, paq1, pwo0, pwo1, palat, palwo, out, L, DIM, DIM);
}

// round 7
// speedup vs baseline: 3.0445x; 3.0445x over previous
#include <cuda_runtime.h>
#include <cuda_fp16.h>
#include <cstdint>
#include <math.h>

// Problem constants
#define L      2048
#define DIM    4096
#define NH     32
#define NKV    8
#define HD     128
#define QDIM   (NH*HD)    // 4096
#define KVDIM  (NKV*HD)   // 1024
#define ATT_SCALE 0.08838834764831845f  // 128^-0.5

// ---------------------------------------------------------------------------
// Scratch (__device__ globals; no allocations allowed)
// ---------------------------------------------------------------------------
__device__ float g_q[L*QDIM];                 // q fp32 (pre-rope)
__device__ float g_kv[L*2*KVDIM];             // [L][k(1024) | v(1024)] fp32
__device__ float g_attn[L*QDIM];              // attention output fp32
__device__ __half g_qh[L*QDIM];               // q fp16, roped, *ATT_SCALE
__device__ __half g_kh[L*KVDIM];              // k fp16, roped
__device__ __half g_vh[L*KVDIM];              // v fp16

// fp16 limbs (activations: hi+lo; weights: single limb, transposed)
__device__ __half g_xh[L*DIM],  g_xl[L*DIM];
__device__ __half g_ah[L*QDIM], g_al[L*QDIM];
__device__ __half g_wqT[DIM*QDIM];        // wq^T  [N=4096][K=4096]
__device__ __half g_wkvT[2*KVDIM*DIM];    // (wk|wv)^T [N=2048][K=4096]
__device__ __half g_woT[QDIM*DIM];        // wo^T  [N=4096][K=4096]

// ---------------------------------------------------------------------------
// PTX helpers (sm_80-era; valid on base compute_103 target)
// ---------------------------------------------------------------------------
__device__ __forceinline__ uint32_t smem_u32(const void* p) {
    uint32_t a;
    asm("{ .reg .u64 t; cvta.to.shared.u64 t, %1; cvt.u32.u64 %0, t; }" : "=r"(a) : "l"(p));
    return a;
}
__device__ __forceinline__ void cp16(void* smem, const void* g) {
    uint32_t s = smem_u32(smem);
    asm volatile("cp.async.cg.shared.global [%0], [%1], 16;" :: "r"(s), "l"(g));
}
#define CP_COMMIT() asm volatile("cp.async.commit_group;")
#define CP_WAIT0()  asm volatile("cp.async.wait_group 0;")
#define CP_WAIT1()  asm volatile("cp.async.wait_group 1;")

__device__ __forceinline__ void ldsm4(uint32_t* r, uint32_t addr) {
    asm volatile("ldmatrix.sync.aligned.m8n8.x4.shared.b16 {%0,%1,%2,%3}, [%4];"
                 : "=r"(r[0]), "=r"(r[1]), "=r"(r[2]), "=r"(r[3]) : "r"(addr));
}
__device__ __forceinline__ void ldsm4t(uint32_t* r, uint32_t addr) {
    asm volatile("ldmatrix.sync.aligned.m8n8.x4.trans.shared.b16 {%0,%1,%2,%3}, [%4];"
                 : "=r"(r[0]), "=r"(r[1]), "=r"(r[2]), "=r"(r[3]) : "r"(addr));
}
__device__ __forceinline__ void mma_f16(float* c, const uint32_t* a, const uint32_t* b) {
    asm volatile("mma.sync.aligned.m16n8k16.row.col.f32.f16.f16.f32 "
                 "{%0,%1,%2,%3},{%4,%5,%6,%7},{%8,%9},{%0,%1,%2,%3};"
                 : "+f"(c[0]), "+f"(c[1]), "+f"(c[2]), "+f"(c[3])
                 : "r"(a[0]), "r"(a[1]), "r"(a[2]), "r"(a[3]), "r"(b[0]), "r"(b[1]));
}
__device__ __forceinline__ uint32_t pack_h2(float lo, float hi) {
    uint32_t r;
    asm("cvt.rn.f16x2.f32 %0, %1, %2;" : "=r"(r) : "f"(hi), "f"(lo));
    return r;
}

// ---------------------------------------------------------------------------
// fp32 -> fp16 hi + fp16 lo split (activations)
// ---------------------------------------------------------------------------
__global__ void split_h(const float* __restrict__ x,
                        __half* __restrict__ h, __half* __restrict__ l, long n)
{
    long i = ((long)blockIdx.x * blockDim.x + threadIdx.x) * 4;
    if (i >= n) return;
    float4 v = *(const float4*)(x + i);
    float vv[4] = {v.x, v.y, v.z, v.w};
    __half hh[4], ll[4];
    #pragma unroll
    for (int j = 0; j < 4; j++) {
        hh[j] = __float2half_rn(vv[j]);
        ll[j] = __float2half_rn(vv[j] - __half2float(hh[j]));
    }
    *(__half2*)(h + i)     = __halves2half2(hh[0], hh[1]);
    *(__half2*)(h + i + 2) = __halves2half2(hh[2], hh[3]);
    *(__half2*)(l + i)     = __halves2half2(ll[0], ll[1]);
    *(__half2*)(l + i + 2) = __halves2half2(ll[2], ll[3]);
}

// Transpose + convert: W fp32 [K][N] -> fp16 [N][K]
__global__ void transT_h(const float* __restrict__ W, __half* __restrict__ H,
                         int K, int N)
{
    __shared__ float t[32][33];
    int n0 = blockIdx.x * 32, k0 = blockIdx.y * 32;
    int tx = threadIdx.x, ty = threadIdx.y;
    #pragma unroll
    for (int r = ty; r < 32; r += 8)
        t[r][tx] = W[(size_t)(k0 + r) * N + n0 + tx];
    __syncthreads();
    #pragma unroll
    for (int r = ty; r < 32; r += 8)
        H[(size_t)(n0 + r) * K + k0 + tx] = __float2half_rn(t[tx][r]);
}

// ---------------------------------------------------------------------------
// fp16 2x1-limb GEMM: C[M,N] = (Ah+Al)[M,K] @ B^T[N,K], fp32 out.
// Block 128x128, BK=64, 8 warps (2M x 4N), warp tile 64x32.
// smem stride 72 halves; 2-stage cp.async; 2 mma per k16 slice.
// ---------------------------------------------------------------------------
#define GST   72                 // halves per smem row
#define GBUFB (128*GST*2)        // bytes per stage per array = 18432

__global__ __launch_bounds__(256, 1) void gemm_h2(
    const __half* __restrict__ Ah, const __half* __restrict__ Al,
    const __half* __restrict__ B,
    float* __restrict__ C, int M, int N, int K)
{
    extern __shared__ char dyn_smem[];
    const uint32_t sb = smem_u32(dyn_smem);
    const int tid = threadIdx.x, lane = tid & 31, wid = tid >> 5;
    const int wm = (wid & 1) * 64, wn = (wid >> 1) * 32;
    const int lrow = lane & 15, lcol = (lane >> 4) * 8;
    const int m0 = blockIdx.y * 128, n0 = blockIdx.x * 128;

    const __half* gAh = Ah + (size_t)m0 * K;
    const __half* gAl = Al + (size_t)m0 * K;
    const __half* gB  = B  + (size_t)n0 * K;

    float acc[4][4][4] = {};
    const int nit = K / 64;

    auto load_stage = [&](int it) {
        const int s = it & 1;
        const int k0 = it * 64;
        for (int i = tid; i < 1024; i += 256) {
            int row = i >> 3, c = i & 7;           // 8 chunks of 16B = 64 halves/row
            uint32_t so = (uint32_t)(row * 144 + c * 16);
            size_t go = (size_t)row * K + k0 + c * 8;
            cp16(dyn_smem + (0 * 2 + s) * GBUFB + so, gAh + go);
            cp16(dyn_smem + (1 * 2 + s) * GBUFB + so, gAl + go);
            cp16(dyn_smem + (2 * 2 + s) * GBUFB + so, gB + go);
        }
        CP_COMMIT();
    };

    load_stage(0);

    for (int it = 0; it < nit; it++) {
        const int s = it & 1;
        if (it + 1 < nit) { load_stage(it + 1); CP_WAIT1(); }
        else              { CP_WAIT0(); }
        __syncthreads();

        const uint32_t aHb = sb + (uint32_t)((0 * 2 + s) * GBUFB);
        const uint32_t aLb = sb + (uint32_t)((1 * 2 + s) * GBUFB);
        const uint32_t bb  = sb + (uint32_t)((2 * 2 + s) * GBUFB);

        #pragma unroll
        for (int ks = 0; ks < 4; ks++) {
            uint32_t ah[4][4], al[4][4], bf[4][2];
            #pragma unroll
            for (int mi = 0; mi < 4; mi++) {
                uint32_t off = (uint32_t)((wm + mi * 16 + lrow) * GST + ks * 16 + lcol) * 2;
                ldsm4(ah[mi], aHb + off);
                ldsm4(al[mi], aLb + off);
            }
            #pragma unroll
            for (int nh = 0; nh < 2; nh++) {
                uint32_t off = (uint32_t)((wn + nh * 16 + lrow) * GST + ks * 16 + lcol) * 2;
                uint32_t r[4];
                ldsm4(r, bb + off);
                bf[nh*2][0] = r[0]; bf[nh*2][1] = r[2];
                bf[nh*2+1][0] = r[1]; bf[nh*2+1][1] = r[3];
            }
            #pragma unroll
            for (int mi = 0; mi < 4; mi++)
                #pragma unroll
                for (int nj = 0; nj < 4; nj++) {
                    mma_f16(acc[mi][nj], ah[mi], bf[nj]);
                    mma_f16(acc[mi][nj], al[mi], bf[nj]);
                }
        }
        __syncthreads();
    }

    // Epilogue
    const int g = lane >> 2;
    #pragma unroll
    for (int mi = 0; mi < 4; mi++) {
        #pragma unroll
        for (int nj = 0; nj < 4; nj++) {
            int row = m0 + wm + mi * 16 + g;
            int col = n0 + wn + nj * 8 + 2 * (lane & 3);
            *(float2*)&C[(size_t)row * N + col] =
                make_float2(acc[mi][nj][0], acc[mi][nj][1]);
            *(float2*)&C[(size_t)(row + 8) * N + col] =
                make_float2(acc[mi][nj][2], acc[mi][nj][3]);
        }
    }
}

// ---------------------------------------------------------------------------
// RoPE kernels (interleaved rotation, concat-layout angles)
// ---------------------------------------------------------------------------
__global__ void rope_q_kernel(const float* __restrict__ q, __half* __restrict__ qh)
{
    long idx = (long)blockIdx.x * blockDim.x + threadIdx.x;  // L*NH*64 pairs
    if (idx >= (long)L * NH * 64) return;
    int  p  = (int)(idx & 63);
    long th = idx >> 6;                 // t*NH + h
    int  t  = (int)(th >> 5);

    const float Cc = 0.14391156644565413f; // ln(10000)/64
    int j0 = 2 * p, j1 = 2 * p + 1;
    float a0 = (float)t * expf(-Cc * (float)(j0 & 63));
    float a1 = (float)t * expf(-Cc * (float)(j1 & 63));
    float c0, s0, c1, s1;
    sincosf(a0, &s0, &c0);
    sincosf(a1, &s1, &c1);

    const float* base = q + th * 128;
    float x0 = base[j0], x1 = base[j1];
    float y0 = (x0 * c0 - x1 * s0) * ATT_SCALE;
    float y1 = (x1 * c1 + x0 * s1) * ATT_SCALE;
    *(__half2*)(qh + th * 128 + j0) = __floats2half2_rn(y0, y1);
}

__global__ void rope_k_kernel(float* __restrict__ kv, __half* __restrict__ kh)
{
    long idx = (long)blockIdx.x * blockDim.x + threadIdx.x;  // L*NKV*64 pairs
    if (idx >= (long)L * NKV * 64) return;
    int  p  = (int)(idx & 63);
    long th = idx >> 6;                 // t*NKV + hk
    int  t  = (int)(th >> 3);
    int  hk = (int)(th & 7);

    const float Cc = 0.14391156644565413f;
    int j0 = 2 * p, j1 = 2 * p + 1;
    float a0 = (float)t * expf(-Cc * (float)(j0 & 63));
    float a1 = (float)t * expf(-Cc * (float)(j1 & 63));
    float c0, s0, c1, s1;
    sincosf(a0, &s0, &c0);
    sincosf(a1, &s1, &c1);

    float* base = kv + (size_t)t * 2048 + hk * 128;
    float x0 = base[j0], x1 = base[j1];
    float y0 = x0 * c0 - x1 * s0;
    float y1 = x1 * c1 + x0 * s1;
    base[j0] = y0;
    base[j1] = y1;
    *(__half2*)(kh + (size_t)t * KVDIM + hk * 128 + j0) = __floats2half2_rn(y0, y1);
}

__global__ void conv_vh_kernel(const float* __restrict__ kv, __half* __restrict__ vh)
{
    long idx = ((long)blockIdx.x * blockDim.x + threadIdx.x) * 2;
    if (idx >= (long)L * KVDIM) return;
    int t = (int)(idx >> 10), j = (int)(idx & 1023);
    float2 v = *(const float2*)(kv + (size_t)t * 2048 + 1024 + j);
    *(__half2*)(vh + idx) = __floats2half2_rn(v.x, v.y);
}

__global__ void write_kv_kernel(const float* __restrict__ kv,
                                float* __restrict__ ok, float* __restrict__ ov)
{
    long idx = (long)blockIdx.x * blockDim.x + threadIdx.x;
    const long total = (long)NH * L * HD;
    if (idx >= total) return;
    int h = (int)(idx >> 18);
    int rem = (int)(idx & 262143);
    int t = rem >> 7;
    int d = rem & 127;
    long src = (long)t * 2048 + (h >> 2) * HD + d;
    ok[idx] = kv[src];
    ov[idx] = kv[src + 1024];
}

// ---------------------------------------------------------------------------
// Flash attention on mma.sync fp16 (unchanged, proven in round 5).
// ---------------------------------------------------------------------------
#define QS_ST 136
#define KV_ST 136
#define KOFF  (128*QS_ST)            // halves
#define VOFF  (KOFF + 2*64*KV_ST)
#define ATT_SMEM ((KOFF + 4*64*KV_ST) * 2)   // bytes = 104448

__global__ __launch_bounds__(256, 1) void attn_mma(
    const __half* __restrict__ qh, const __half* __restrict__ kh,
    const __half* __restrict__ vh, float* __restrict__ o)
{
    extern __shared__ char dyn_smem[];
    __half* smh = (__half*)dyn_smem;
    const uint32_t sb = smem_u32(smh);
    const int tid = threadIdx.x, lane = tid & 31, wid = tid >> 5;
    const int h = blockIdx.y, qt = blockIdx.x, kvh = h >> 2;
    const int g = lane >> 2;
    const int lrow = lane & 15, lcol = (lane >> 4) * 8;

    for (int i = tid; i < 2048; i += 256) {
        int r = i >> 4, c = i & 15;
        cp16(smh + r * QS_ST + c * 8,
             qh + (size_t)(qt * 128 + r) * QDIM + h * HD + c * 8);
    }
    CP_COMMIT(); CP_WAIT0();
    __syncthreads();
    uint32_t aQ[8][4];
    #pragma unroll
    for (int ks = 0; ks < 8; ks++)
        ldsm4(aQ[ks], sb + (uint32_t)((wid * 16 + lrow) * QS_ST + ks * 16 + lcol) * 2);

    auto load_kv = [&](int kt) {
        const int s = kt & 1;
        const __half* kg = kh + (size_t)(kt * 64) * KVDIM + kvh * HD;
        const __half* vg = vh + (size_t)(kt * 64) * KVDIM + kvh * HD;
        __half* ksm = smh + KOFF + s * (64 * KV_ST);
        __half* vsm = smh + VOFF + s * (64 * KV_ST);
        for (int i = tid; i < 1024; i += 256) {
            int r = i >> 4, c = i & 15;
            cp16(ksm + r * KV_ST + c * 8, kg + (size_t)r * KVDIM + c * 8);
            cp16(vsm + r * KV_ST + c * 8, vg + (size_t)r * KVDIM + c * 8);
        }
        CP_COMMIT();
    };

    float O[16][4] = {};
    float m0 = -1e30f, m1 = -1e30f, l0 = 0.f, l1 = 0.f;

    load_kv(0);

    for (int kt = 0; kt < 32; kt++) {
        if (kt + 1 < 32) { load_kv(kt + 1); CP_WAIT1(); }
        else             { CP_WAIT0(); }
        __syncthreads();

        const uint32_t kbase = sb + (uint32_t)(KOFF + (kt & 1) * (64 * KV_ST)) * 2;
        const uint32_t vbase = sb + (uint32_t)(VOFF + (kt & 1) * (64 * KV_ST)) * 2;

        float c[8][4] = {};
        #pragma unroll
        for (int ks = 0; ks < 8; ks++) {
            #pragma unroll
            for (int nh = 0; nh < 4; nh++) {
                uint32_t r[4];
                ldsm4(r, kbase + (uint32_t)((nh * 16 + lrow) * KV_ST + ks * 16 + lcol) * 2);
                uint32_t b0[2] = {r[0], r[2]};
                uint32_t b1[2] = {r[1], r[3]};
                mma_f16(c[nh * 2],     aQ[ks], b0);
                mma_f16(c[nh * 2 + 1], aQ[ks], b1);
            }
        }

        float mx0 = m0, mx1 = m1;
        #pragma unroll
        for (int t = 0; t < 8; t++) {
            mx0 = fmaxf(mx0, fmaxf(c[t][0], c[t][1]));
            mx1 = fmaxf(mx1, fmaxf(c[t][2], c[t][3]));
        }
        mx0 = fmaxf(mx0, __shfl_xor_sync(0xFFFFFFFF, mx0, 1));
        mx0 = fmaxf(mx0, __shfl_xor_sync(0xFFFFFFFF, mx0, 2));
        mx1 = fmaxf(mx1, __shfl_xor_sync(0xFFFFFFFF, mx1, 1));
        mx1 = fmaxf(mx1, __shfl_xor_sync(0xFFFFFFFF, mx1, 2));
        float f0 = __expf(m0 - mx0), f1 = __expf(m1 - mx1);
        m0 = mx0; m1 = mx1;
        float s0 = 0.f, s1 = 0.f;
        #pragma unroll
        for (int t = 0; t < 8; t++) {
            c[t][0] = __expf(c[t][0] - m0); s0 += c[t][0];
            c[t][1] = __expf(c[t][1] - m0); s0 += c[t][1];
            c[t][2] = __expf(c[t][2] - m1); s1 += c[t][2];
            c[t][3] = __expf(c[t][3] - m1); s1 += c[t][3];
        }
        s0 += __shfl_xor_sync(0xFFFFFFFF, s0, 1);
        s0 += __shfl_xor_sync(0xFFFFFFFF, s0, 2);
        s1 += __shfl_xor_sync(0xFFFFFFFF, s1, 1);
        s1 += __shfl_xor_sync(0xFFFFFFFF, s1, 2);
        l0 = l0 * f0 + s0;
        l1 = l1 * f1 + s1;

        #pragma unroll
        for (int t = 0; t < 16; t++) {
            O[t][0] *= f0; O[t][1] *= f0;
            O[t][2] *= f1; O[t][3] *= f1;
        }

        #pragma unroll
        for (int k2 = 0; k2 < 4; k2++) {
            uint32_t a[4];
            a[0] = pack_h2(c[2 * k2][0],     c[2 * k2][1]);
            a[1] = pack_h2(c[2 * k2][2],     c[2 * k2][3]);
            a[2] = pack_h2(c[2 * k2 + 1][0], c[2 * k2 + 1][1]);
            a[3] = pack_h2(c[2 * k2 + 1][2], c[2 * k2 + 1][3]);
            #pragma unroll
            for (int dj = 0; dj < 8; dj++) {
                uint32_t r[4];
                ldsm4t(r, vbase + (uint32_t)((k2 * 16 + lrow) * KV_ST + dj * 16 + lcol) * 2);
                uint32_t b0[2] = {r[0], r[1]};
                uint32_t b1[2] = {r[2], r[3]};
                mma_f16(O[dj * 2],     a, b0);
                mma_f16(O[dj * 2 + 1], a, b1);
            }
        }
        __syncthreads();
    }

    float inv0 = 1.f / l0, inv1 = 1.f / l1;
    const int row0 = qt * 128 + wid * 16 + g;
    #pragma unroll
    for (int t = 0; t < 16; t++) {
        float* d0 = o + (size_t)row0 * QDIM + h * HD + t * 8 + 2 * (lane & 3);
        float* d1 = o + (size_t)(row0 + 8) * QDIM + h * HD + t * 8 + 2 * (lane & 3);
        *(float2*)d0 = make_float2(O[t][0] * inv0, O[t][1] * inv0);
        *(float2*)d1 = make_float2(O[t][2] * inv1, O[t][3] * inv1);
    }
}

// ---------------------------------------------------------------------------
// Launch
// ---------------------------------------------------------------------------
extern "C" void kernel_launch(void* const* d_in, const int* in_sizes, int n_in,
                              void* d_out, int out_size)
{
    const float* x  = (const float*)d_in[0];
    const float* wq = (const float*)d_in[1];
    const float* wk = (const float*)d_in[2];
    const float* wv = (const float*)d_in[3];
    const float* wo = (const float*)d_in[4];
    float* out = (float*)d_out;

    float *pq, *pkv, *pattn;
    __half *pqh, *pkh, *pvh;
    __half *pxh, *pxl, *pah, *pal, *pwqT, *pwkvT, *pwoT;
    cudaGetSymbolAddress((void**)&pq,    g_q);
    cudaGetSymbolAddress((void**)&pkv,   g_kv);
    cudaGetSymbolAddress((void**)&pattn, g_attn);
    cudaGetSymbolAddress((void**)&pqh,   g_qh);
    cudaGetSymbolAddress((void**)&pkh,   g_kh);
    cudaGetSymbolAddress((void**)&pvh,   g_vh);
    cudaGetSymbolAddress((void**)&pxh,   g_xh);
    cudaGetSymbolAddress((void**)&pxl,   g_xl);
    cudaGetSymbolAddress((void**)&pah,   g_ah);
    cudaGetSymbolAddress((void**)&pal,   g_al);
    cudaGetSymbolAddress((void**)&pwqT,  g_wqT);
    cudaGetSymbolAddress((void**)&pwkvT, g_wkvT);
    cudaGetSymbolAddress((void**)&pwoT,  g_woT);

    const int gemm_smem = 6 * GBUFB;   // 110592 B
    cudaFuncSetAttribute(gemm_h2, cudaFuncAttributeMaxDynamicSharedMemorySize, gemm_smem);
    cudaFuncSetAttribute(attn_mma, cudaFuncAttributeMaxDynamicSharedMemorySize, ATT_SMEM);

    dim3 thr32x8(32, 8);

    // 1) Convert inputs: x -> fp16 hi/lo; weights -> fp16 transposed
    {
        long nx = (long)L * DIM;
        split_h<<<(unsigned)(nx / (256 * 4)), 256>>>(x, pxh, pxl, nx);
        transT_h<<<dim3(QDIM / 32, DIM / 32), thr32x8>>>(wq, pwqT, DIM, QDIM);
        transT_h<<<dim3(KVDIM / 32, DIM / 32), thr32x8>>>(wk, pwkvT, DIM, KVDIM);
        transT_h<<<dim3(KVDIM / 32, DIM / 32), thr32x8>>>(wv, pwkvT + (size_t)KVDIM * DIM, DIM, KVDIM);
        transT_h<<<dim3(DIM / 32, QDIM / 32), thr32x8>>>(wo, pwoT, QDIM, DIM);
    }

    // 2) Projections: q = x@wq ; kv = x@(wk|wv)
    gemm_h2<<<dim3(QDIM / 128, L / 128), 256, gemm_smem>>>(pxh, pxl, pwqT, pq, L, QDIM, DIM);
    gemm_h2<<<dim3(2 * KVDIM / 128, L / 128), 256, gemm_smem>>>(pxh, pxl, pwkvT, pkv, L, 2 * KVDIM, DIM);

    // 3) RoPE + fp16 conversions
    {
        long pq_pairs = (long)L * NH * 64;
        long pk_pairs = (long)L * NKV * 64;
        rope_q_kernel<<<(unsigned)((pq_pairs + 255) / 256), 256>>>(pq, pqh);
        rope_k_kernel<<<(unsigned)((pk_pairs + 255) / 256), 256>>>(pkv, pkh);
        long nv = (long)L * KVDIM / 2;
        conv_vh_kernel<<<(unsigned)((nv + 255) / 256), 256>>>(pkv, pvh);
    }

    // 4) Emit repeated (k, v) output sections
    const long OUT0 = (long)L * QDIM;
    const long KVSZ = (long)NH * L * HD;
    if ((long)out_size >= OUT0 + 2 * KVSZ) {
        write_kv_kernel<<<(unsigned)((KVSZ + 255) / 256), 256>>>(pkv, out + OUT0, out + OUT0 + KVSZ);
    }

    // 5) Flash attention (fp16 mma)
    attn_mma<<<dim3(L / 128, NH), 256, ATT_SMEM>>>(pqh, pkh, pvh, pattn);

    // 6) Split attention output, final projection
    {
        long na = (long)L * QDIM;
        split_h<<<(unsigned)(na / (256 * 4)), 256>>>(pattn, pah, pal, na);
    }
    gemm_h2<<<dim3(DIM / 128, L / 128), 256, gemm_smem>>>(pah, pal, pwoT, out, L, DIM, DIM);
}

// round 8
// speedup vs baseline: 3.0954x; 1.0167x over previous
#include <cuda_runtime.h>
#include <cuda_fp16.h>
#include <cstdint>
#include <math.h>

// Problem constants
#define L      2048
#define DIM    4096
#define NH     32
#define NKV    8
#define HD     128
#define QDIM   (NH*HD)    // 4096
#define KVDIM  (NKV*HD)   // 1024
#define ATT_SCALE 0.08838834764831845f  // 128^-0.5

// ---------------------------------------------------------------------------
// Scratch (__device__ globals; no allocations allowed)
// ---------------------------------------------------------------------------
__device__ float g_q[L*QDIM];                 // q fp32 (pre-rope)
__device__ float g_kv[L*2*KVDIM];             // [L][k(1024) | v(1024)] fp32
__device__ __half g_qh[L*QDIM];               // q fp16, roped, *ATT_SCALE
__device__ __half g_kh[L*KVDIM];              // k fp16, roped
__device__ __half g_vh[L*KVDIM];              // v fp16

// fp16 limbs (activations: hi+lo; weights: single limb, transposed)
__device__ __half g_xh[L*DIM],  g_xl[L*DIM];
__device__ __half g_ah[L*QDIM], g_al[L*QDIM];   // attention output hi/lo (written by attn)
__device__ __half g_wqT[DIM*QDIM];        // wq^T  [N=4096][K=4096]
__device__ __half g_wkvT[2*KVDIM*DIM];    // (wk|wv)^T [N=2048][K=4096]
__device__ __half g_woT[QDIM*DIM];        // wo^T  [N=4096][K=4096]

// ---------------------------------------------------------------------------
// PTX helpers (sm_80-era; valid on base compute_103 target)
// ---------------------------------------------------------------------------
__device__ __forceinline__ uint32_t smem_u32(const void* p) {
    uint32_t a;
    asm("{ .reg .u64 t; cvta.to.shared.u64 t, %1; cvt.u32.u64 %0, t; }" : "=r"(a) : "l"(p));
    return a;
}
__device__ __forceinline__ void cp16(void* smem, const void* g) {
    uint32_t s = smem_u32(smem);
    asm volatile("cp.async.cg.shared.global [%0], [%1], 16;" :: "r"(s), "l"(g));
}
#define CP_COMMIT() asm volatile("cp.async.commit_group;")
#define CP_WAIT0()  asm volatile("cp.async.wait_group 0;")

__device__ __forceinline__ void ldsm4(uint32_t* r, uint32_t addr) {
    asm volatile("ldmatrix.sync.aligned.m8n8.x4.shared.b16 {%0,%1,%2,%3}, [%4];"
                 : "=r"(r[0]), "=r"(r[1]), "=r"(r[2]), "=r"(r[3]) : "r"(addr));
}
__device__ __forceinline__ void ldsm4t(uint32_t* r, uint32_t addr) {
    asm volatile("ldmatrix.sync.aligned.m8n8.x4.trans.shared.b16 {%0,%1,%2,%3}, [%4];"
                 : "=r"(r[0]), "=r"(r[1]), "=r"(r[2]), "=r"(r[3]) : "r"(addr));
}
__device__ __forceinline__ void mma_f16(float* c, const uint32_t* a, const uint32_t* b) {
    asm volatile("mma.sync.aligned.m16n8k16.row.col.f32.f16.f16.f32 "
                 "{%0,%1,%2,%3},{%4,%5,%6,%7},{%8,%9},{%0,%1,%2,%3};"
                 : "+f"(c[0]), "+f"(c[1]), "+f"(c[2]), "+f"(c[3])
                 : "r"(a[0]), "r"(a[1]), "r"(a[2]), "r"(a[3]), "r"(b[0]), "r"(b[1]));
}
__device__ __forceinline__ uint32_t pack_h2(float lo, float hi) {
    uint32_t r;
    asm("cvt.rn.f16x2.f32 %0, %1, %2;" : "=r"(r) : "f"(hi), "f"(lo));
    return r;
}

// ---------------------------------------------------------------------------
// fp32 -> fp16 hi + fp16 lo split (x input)
// ---------------------------------------------------------------------------
__global__ void split_h(const float* __restrict__ x,
                        __half* __restrict__ h, __half* __restrict__ l, long n)
{
    long i = ((long)blockIdx.x * blockDim.x + threadIdx.x) * 4;
    if (i >= n) return;
    float4 v = *(const float4*)(x + i);
    float vv[4] = {v.x, v.y, v.z, v.w};
    __half hh[4], ll[4];
    #pragma unroll
    for (int j = 0; j < 4; j++) {
        hh[j] = __float2half_rn(vv[j]);
        ll[j] = __float2half_rn(vv[j] - __half2float(hh[j]));
    }
    *(__half2*)(h + i)     = __halves2half2(hh[0], hh[1]);
    *(__half2*)(h + i + 2) = __halves2half2(hh[2], hh[3]);
    *(__half2*)(l + i)     = __halves2half2(ll[0], ll[1]);
    *(__half2*)(l + i + 2) = __halves2half2(ll[2], ll[3]);
}

// Transpose + convert: W fp32 [K][N] -> fp16 [N][K]
__global__ void transT_h(const float* __restrict__ W, __half* __restrict__ H,
                         int K, int N)
{
    __shared__ float t[32][33];
    int n0 = blockIdx.x * 32, k0 = blockIdx.y * 32;
    int tx = threadIdx.x, ty = threadIdx.y;
    #pragma unroll
    for (int r = ty; r < 32; r += 8)
        t[r][tx] = W[(size_t)(k0 + r) * N + n0 + tx];
    __syncthreads();
    #pragma unroll
    for (int r = ty; r < 32; r += 8)
        H[(size_t)(n0 + r) * K + k0 + tx] = __float2half_rn(t[tx][r]);
}

// ---------------------------------------------------------------------------
// fp16 2x1-limb GEMM: C[M,N] = (Ah+Al)[M,K] @ B^T[N,K], fp32 out.
// Block 128x256, BK=64, 8 warps (2M x 4N), warp tile 64x64.
// smem rows 144B (72 halves); race-free single-lookahead cp.async pipeline.
// ---------------------------------------------------------------------------
#define GST    72                 // halves per smem row
#define A_STGB 18432              // bytes per A limb per stage (128*144)
#define B_STGB 36864              // bytes for B per stage (256*144)
#define STGB   (2*A_STGB + B_STGB)   // 73728 per stage
#define GEMM_SMEM (2*STGB)        // 147456

__global__ __launch_bounds__(256, 1) void gemm_h2(
    const __half* __restrict__ Ah, const __half* __restrict__ Al,
    const __half* __restrict__ B,
    float* __restrict__ C, int M, int N, int K)
{
    extern __shared__ char dyn_smem[];
    const uint32_t sb = smem_u32(dyn_smem);
    const int tid = threadIdx.x, lane = tid & 31, wid = tid >> 5;
    const int wm = (wid & 1) * 64, wn = (wid >> 1) * 64;
    const int lrow = lane & 15, lcol = (lane >> 4) * 8;
    const int m0 = blockIdx.y * 128, n0 = blockIdx.x * 256;

    const __half* gAh = Ah + (size_t)m0 * K;
    const __half* gAl = Al + (size_t)m0 * K;
    const __half* gB  = B  + (size_t)n0 * K;

    float acc[4][8][4] = {};
    const int nit = K / 64;

    auto load_stage = [&](int it) {
        const int s = it & 1;
        const int k0 = it * 64;
        char* base = dyn_smem + s * STGB;
        for (int i = tid; i < 1024; i += 256) {      // A rows (both limbs)
            int row = i >> 3, c = i & 7;
            uint32_t so = (uint32_t)(row * 144 + c * 16);
            size_t go = (size_t)row * K + k0 + c * 8;
            cp16(base + so, gAh + go);
            cp16(base + A_STGB + so, gAl + go);
        }
        for (int i = tid; i < 2048; i += 256) {      // B rows
            int row = i >> 3, c = i & 7;
            cp16(base + 2 * A_STGB + row * 144 + c * 16,
                 gB + (size_t)row * K + k0 + c * 8);
        }
        CP_COMMIT();
    };

    load_stage(0);

    for (int it = 0; it < nit; it++) {
        const int s = it & 1;
        CP_WAIT0();
        __syncthreads();
        if (it + 1 < nit) load_stage(it + 1);

        const uint32_t aHb = sb + (uint32_t)(s * STGB);
        const uint32_t aLb = aHb + A_STGB;
        const uint32_t bb  = aHb + 2 * A_STGB;

        #pragma unroll
        for (int ks = 0; ks < 4; ks++) {
            uint32_t ah[4][4], al[4][4], bf[8][2];
            #pragma unroll
            for (int mi = 0; mi < 4; mi++) {
                uint32_t off = (uint32_t)((wm + mi * 16 + lrow) * GST + ks * 16 + lcol) * 2;
                ldsm4(ah[mi], aHb + off);
                ldsm4(al[mi], aLb + off);
            }
            #pragma unroll
            for (int nh = 0; nh < 4; nh++) {
                uint32_t off = (uint32_t)((wn + nh * 16 + lrow) * GST + ks * 16 + lcol) * 2;
                uint32_t r[4];
                ldsm4(r, bb + off);
                bf[nh*2][0] = r[0]; bf[nh*2][1] = r[2];
                bf[nh*2+1][0] = r[1]; bf[nh*2+1][1] = r[3];
            }
            #pragma unroll
            for (int mi = 0; mi < 4; mi++)
                #pragma unroll
                for (int nj = 0; nj < 8; nj++) {
                    mma_f16(acc[mi][nj], ah[mi], bf[nj]);
                    mma_f16(acc[mi][nj], al[mi], bf[nj]);
                }
        }
    }

    // Epilogue
    const int g = lane >> 2;
    #pragma unroll
    for (int mi = 0; mi < 4; mi++) {
        #pragma unroll
        for (int nj = 0; nj < 8; nj++) {
            int row = m0 + wm + mi * 16 + g;
            int col = n0 + wn + nj * 8 + 2 * (lane & 3);
            *(float2*)&C[(size_t)row * N + col] =
                make_float2(acc[mi][nj][0], acc[mi][nj][1]);
            *(float2*)&C[(size_t)(row + 8) * N + col] =
                make_float2(acc[mi][nj][2], acc[mi][nj][3]);
        }
    }
}

// ---------------------------------------------------------------------------
// RoPE kernels (interleaved rotation, concat-layout angles)
// ---------------------------------------------------------------------------
__global__ void rope_q_kernel(const float* __restrict__ q, __half* __restrict__ qh)
{
    long idx = (long)blockIdx.x * blockDim.x + threadIdx.x;  // L*NH*64 pairs
    if (idx >= (long)L * NH * 64) return;
    int  p  = (int)(idx & 63);
    long th = idx >> 6;                 // t*NH + h
    int  t  = (int)(th >> 5);

    const float Cc = 0.14391156644565413f; // ln(10000)/64
    int j0 = 2 * p, j1 = 2 * p + 1;
    float a0 = (float)t * expf(-Cc * (float)(j0 & 63));
    float a1 = (float)t * expf(-Cc * (float)(j1 & 63));
    float c0, s0, c1, s1;
    sincosf(a0, &s0, &c0);
    sincosf(a1, &s1, &c1);

    const float* base = q + th * 128;
    float x0 = base[j0], x1 = base[j1];
    float y0 = (x0 * c0 - x1 * s0) * ATT_SCALE;
    float y1 = (x1 * c1 + x0 * s1) * ATT_SCALE;
    *(__half2*)(qh + th * 128 + j0) = __floats2half2_rn(y0, y1);
}

__global__ void rope_k_kernel(float* __restrict__ kv, __half* __restrict__ kh)
{
    long idx = (long)blockIdx.x * blockDim.x + threadIdx.x;  // L*NKV*64 pairs
    if (idx >= (long)L * NKV * 64) return;
    int  p  = (int)(idx & 63);
    long th = idx >> 6;                 // t*NKV + hk
    int  t  = (int)(th >> 3);
    int  hk = (int)(th & 7);

    const float Cc = 0.14391156644565413f;
    int j0 = 2 * p, j1 = 2 * p + 1;
    float a0 = (float)t * expf(-Cc * (float)(j0 & 63));
    float a1 = (float)t * expf(-Cc * (float)(j1 & 63));
    float c0, s0, c1, s1;
    sincosf(a0, &s0, &c0);
    sincosf(a1, &s1, &c1);

    float* base = kv + (size_t)t * 2048 + hk * 128;
    float x0 = base[j0], x1 = base[j1];
    float y0 = x0 * c0 - x1 * s0;
    float y1 = x1 * c1 + x0 * s1;
    base[j0] = y0;
    base[j1] = y1;
    *(__half2*)(kh + (size_t)t * KVDIM + hk * 128 + j0) = __floats2half2_rn(y0, y1);
}

__global__ void conv_vh_kernel(const float* __restrict__ kv, __half* __restrict__ vh)
{
    long idx = ((long)blockIdx.x * blockDim.x + threadIdx.x) * 2;
    if (idx >= (long)L * KVDIM) return;
    int t = (int)(idx >> 10), j = (int)(idx & 1023);
    float2 v = *(const float2*)(kv + (size_t)t * 2048 + 1024 + j);
    *(__half2*)(vh + idx) = __floats2half2_rn(v.x, v.y);
}

__global__ void write_kv_kernel(const float* __restrict__ kv,
                                float* __restrict__ ok, float* __restrict__ ov)
{
    long idx = (long)blockIdx.x * blockDim.x + threadIdx.x;
    const long total = (long)NH * L * HD;
    if (idx >= total) return;
    int h = (int)(idx >> 18);
    int rem = (int)(idx & 262143);
    int t = rem >> 7;
    int d = rem & 127;
    long src = (long)t * 2048 + (h >> 2) * HD + d;
    ok[idx] = kv[src];
    ov[idx] = kv[src + 1024];
}

// ---------------------------------------------------------------------------
// Flash attention on mma.sync fp16; epilogue writes fp16 hi/lo limbs directly.
// ---------------------------------------------------------------------------
#define QS_ST 136
#define KV_ST 136
#define KOFF  (128*QS_ST)            // halves
#define VOFF  (KOFF + 2*64*KV_ST)
#define ATT_SMEM ((KOFF + 4*64*KV_ST) * 2)   // bytes = 104448

__global__ __launch_bounds__(256, 1) void attn_mma(
    const __half* __restrict__ qh, const __half* __restrict__ kh,
    const __half* __restrict__ vh,
    __half* __restrict__ oh, __half* __restrict__ ol)
{
    extern __shared__ char dyn_smem[];
    __half* smh = (__half*)dyn_smem;
    const uint32_t sb = smem_u32(smh);
    const int tid = threadIdx.x, lane = tid & 31, wid = tid >> 5;
    const int h = blockIdx.y, qt = blockIdx.x, kvh = h >> 2;
    const int g = lane >> 2;
    const int lrow = lane & 15, lcol = (lane >> 4) * 8;

    for (int i = tid; i < 2048; i += 256) {
        int r = i >> 4, c = i & 15;
        cp16(smh + r * QS_ST + c * 8,
             qh + (size_t)(qt * 128 + r) * QDIM + h * HD + c * 8);
    }
    CP_COMMIT(); CP_WAIT0();
    __syncthreads();
    uint32_t aQ[8][4];
    #pragma unroll
    for (int ks = 0; ks < 8; ks++)
        ldsm4(aQ[ks], sb + (uint32_t)((wid * 16 + lrow) * QS_ST + ks * 16 + lcol) * 2);
    __syncthreads();

    auto load_kv = [&](int kt) {
        const int s = kt & 1;
        const __half* kg = kh + (size_t)(kt * 64) * KVDIM + kvh * HD;
        const __half* vg = vh + (size_t)(kt * 64) * KVDIM + kvh * HD;
        __half* ksm = smh + KOFF + s * (64 * KV_ST);
        __half* vsm = smh + VOFF + s * (64 * KV_ST);
        for (int i = tid; i < 1024; i += 256) {
            int r = i >> 4, c = i & 15;
            cp16(ksm + r * KV_ST + c * 8, kg + (size_t)r * KVDIM + c * 8);
            cp16(vsm + r * KV_ST + c * 8, vg + (size_t)r * KVDIM + c * 8);
        }
        CP_COMMIT();
    };

    float O[16][4] = {};
    float m0 = -1e30f, m1 = -1e30f, l0 = 0.f, l1 = 0.f;

    load_kv(0);

    for (int kt = 0; kt < 32; kt++) {
        CP_WAIT0();
        __syncthreads();
        if (kt + 1 < 32) load_kv(kt + 1);

        const uint32_t kbase = sb + (uint32_t)(KOFF + (kt & 1) * (64 * KV_ST)) * 2;
        const uint32_t vbase = sb + (uint32_t)(VOFF + (kt & 1) * (64 * KV_ST)) * 2;

        float c[8][4] = {};
        #pragma unroll
        for (int ks = 0; ks < 8; ks++) {
            #pragma unroll
            for (int nh = 0; nh < 4; nh++) {
                uint32_t r[4];
                ldsm4(r, kbase + (uint32_t)((nh * 16 + lrow) * KV_ST + ks * 16 + lcol) * 2);
                uint32_t b0[2] = {r[0], r[2]};
                uint32_t b1[2] = {r[1], r[3]};
                mma_f16(c[nh * 2],     aQ[ks], b0);
                mma_f16(c[nh * 2 + 1], aQ[ks], b1);
            }
        }

        float mx0 = m0, mx1 = m1;
        #pragma unroll
        for (int t = 0; t < 8; t++) {
            mx0 = fmaxf(mx0, fmaxf(c[t][0], c[t][1]));
            mx1 = fmaxf(mx1, fmaxf(c[t][2], c[t][3]));
        }
        mx0 = fmaxf(mx0, __shfl_xor_sync(0xFFFFFFFF, mx0, 1));
        mx0 = fmaxf(mx0, __shfl_xor_sync(0xFFFFFFFF, mx0, 2));
        mx1 = fmaxf(mx1, __shfl_xor_sync(0xFFFFFFFF, mx1, 1));
        mx1 = fmaxf(mx1, __shfl_xor_sync(0xFFFFFFFF, mx1, 2));
        float f0 = __expf(m0 - mx0), f1 = __expf(m1 - mx1);
        m0 = mx0; m1 = mx1;
        float s0 = 0.f, s1 = 0.f;
        #pragma unroll
        for (int t = 0; t < 8; t++) {
            c[t][0] = __expf(c[t][0] - m0); s0 += c[t][0];
            c[t][1] = __expf(c[t][1] - m0); s0 += c[t][1];
            c[t][2] = __expf(c[t][2] - m1); s1 += c[t][2];
            c[t][3] = __expf(c[t][3] - m1); s1 += c[t][3];
        }
        s0 += __shfl_xor_sync(0xFFFFFFFF, s0, 1);
        s0 += __shfl_xor_sync(0xFFFFFFFF, s0, 2);
        s1 += __shfl_xor_sync(0xFFFFFFFF, s1, 1);
        s1 += __shfl_xor_sync(0xFFFFFFFF, s1, 2);
        l0 = l0 * f0 + s0;
        l1 = l1 * f1 + s1;

        #pragma unroll
        for (int t = 0; t < 16; t++) {
            O[t][0] *= f0; O[t][1] *= f0;
            O[t][2] *= f1; O[t][3] *= f1;
        }

        #pragma unroll
        for (int k2 = 0; k2 < 4; k2++) {
            uint32_t a[4];
            a[0] = pack_h2(c[2 * k2][0],     c[2 * k2][1]);
            a[1] = pack_h2(c[2 * k2][2],     c[2 * k2][3]);
            a[2] = pack_h2(c[2 * k2 + 1][0], c[2 * k2 + 1][1]);
            a[3] = pack_h2(c[2 * k2 + 1][2], c[2 * k2 + 1][3]);
            #pragma unroll
            for (int dj = 0; dj < 8; dj++) {
                uint32_t r[4];
                ldsm4t(r, vbase + (uint32_t)((k2 * 16 + lrow) * KV_ST + dj * 16 + lcol) * 2);
                uint32_t b0[2] = {r[0], r[1]};
                uint32_t b1[2] = {r[2], r[3]};
                mma_f16(O[dj * 2],     a, b0);
                mma_f16(O[dj * 2 + 1], a, b1);
            }
        }
        __syncthreads();
    }

    // Epilogue: normalize and write fp16 hi/lo limbs directly
    float inv0 = 1.f / l0, inv1 = 1.f / l1;
    const int row0 = qt * 128 + wid * 16 + g;
    #pragma unroll
    for (int t = 0; t < 16; t++) {
        size_t o0 = (size_t)row0 * QDIM + h * HD + t * 8 + 2 * (lane & 3);
        size_t o1 = (size_t)(row0 + 8) * QDIM + h * HD + t * 8 + 2 * (lane & 3);
        float y00 = O[t][0] * inv0, y01 = O[t][1] * inv0;
        float y10 = O[t][2] * inv1, y11 = O[t][3] * inv1;
        __half h00 = __float2half_rn(y00), h01 = __float2half_rn(y01);
        __half h10 = __float2half_rn(y10), h11 = __float2half_rn(y11);
        *(__half2*)(oh + o0) = __halves2half2(h00, h01);
        *(__half2*)(oh + o1) = __halves2half2(h10, h11);
        *(__half2*)(ol + o0) = __halves2half2(
            __float2half_rn(y00 - __half2float(h00)),
            __float2half_rn(y01 - __half2float(h01)));
        *(__half2*)(ol + o1) = __halves2half2(
            __float2half_rn(y10 - __half2float(h10)),
            __float2half_rn(y11 - __half2float(h11)));
    }
}

// ---------------------------------------------------------------------------
// Launch
// ---------------------------------------------------------------------------
extern "C" void kernel_launch(void* const* d_in, const int* in_sizes, int n_in,
                              void* d_out, int out_size)
{
    const float* x  = (const float*)d_in[0];
    const float* wq = (const float*)d_in[1];
    const float* wk = (const float*)d_in[2];
    const float* wv = (const float*)d_in[3];
    const float* wo = (const float*)d_in[4];
    float* out = (float*)d_out;

    float *pq, *pkv;
    __half *pqh, *pkh, *pvh;
    __half *pxh, *pxl, *pah, *pal, *pwqT, *pwkvT, *pwoT;
    cudaGetSymbolAddress((void**)&pq,    g_q);
    cudaGetSymbolAddress((void**)&pkv,   g_kv);
    cudaGetSymbolAddress((void**)&pqh,   g_qh);
    cudaGetSymbolAddress((void**)&pkh,   g_kh);
    cudaGetSymbolAddress((void**)&pvh,   g_vh);
    cudaGetSymbolAddress((void**)&pxh,   g_xh);
    cudaGetSymbolAddress((void**)&pxl,   g_xl);
    cudaGetSymbolAddress((void**)&pah,   g_ah);
    cudaGetSymbolAddress((void**)&pal,   g_al);
    cudaGetSymbolAddress((void**)&pwqT,  g_wqT);
    cudaGetSymbolAddress((void**)&pwkvT, g_wkvT);
    cudaGetSymbolAddress((void**)&pwoT,  g_woT);

    cudaFuncSetAttribute(gemm_h2, cudaFuncAttributeMaxDynamicSharedMemorySize, GEMM_SMEM);
    cudaFuncSetAttribute(attn_mma, cudaFuncAttributeMaxDynamicSharedMemorySize, ATT_SMEM);

    dim3 thr32x8(32, 8);

    // 1) Convert inputs: x -> fp16 hi/lo; weights -> fp16 transposed
    {
        long nx = (long)L * DIM;
        split_h<<<(unsigned)(nx / (256 * 4)), 256>>>(x, pxh, pxl, nx);
        transT_h<<<dim3(QDIM / 32, DIM / 32), thr32x8>>>(wq, pwqT, DIM, QDIM);
        transT_h<<<dim3(KVDIM / 32, DIM / 32), thr32x8>>>(wk, pwkvT, DIM, KVDIM);
        transT_h<<<dim3(KVDIM / 32, DIM / 32), thr32x8>>>(wv, pwkvT + (size_t)KVDIM * DIM, DIM, KVDIM);
        transT_h<<<dim3(DIM / 32, QDIM / 32), thr32x8>>>(wo, pwoT, QDIM, DIM);
    }

    // 2) Projections: q = x@wq ; kv = x@(wk|wv)
    gemm_h2<<<dim3(QDIM / 256, L / 128), 256, GEMM_SMEM>>>(pxh, pxl, pwqT, pq, L, QDIM, DIM);
    gemm_h2<<<dim3(2 * KVDIM / 256, L / 128), 256, GEMM_SMEM>>>(pxh, pxl, pwkvT, pkv, L, 2 * KVDIM, DIM);

    // 3) RoPE + fp16 conversions
    {
        long pq_pairs = (long)L * NH * 64;
        long pk_pairs = (long)L * NKV * 64;
        rope_q_kernel<<<(unsigned)((pq_pairs + 255) / 256), 256>>>(pq, pqh);
        rope_k_kernel<<<(unsigned)((pk_pairs + 255) / 256), 256>>>(pkv, pkh);
        long nv = (long)L * KVDIM / 2;
        conv_vh_kernel<<<(unsigned)((nv + 255) / 256), 256>>>(pkv, pvh);
    }

    // 4) Emit repeated (k, v) output sections
    const long OUT0 = (long)L * QDIM;
    const long KVSZ = (long)NH * L * HD;
    if ((long)out_size >= OUT0 + 2 * KVSZ) {
        write_kv_kernel<<<(unsigned)((KVSZ + 255) / 256), 256>>>(pkv, out + OUT0, out + OUT0 + KVSZ);
    }

    // 5) Flash attention (fp16 mma) -> writes fp16 hi/lo limbs directly
    attn_mma<<<dim3(L / 128, NH), 256, ATT_SMEM>>>(pqh, pkh, pvh, pah, pal);

    // 6) Final projection
    gemm_h2<<<dim3(DIM / 256, L / 128), 256, GEMM_SMEM>>>(pah, pal, pwoT, out, L, DIM, DIM);
}